// round 13
// baseline (speedup 1.0000x reference)
#include <cuda_runtime.h>
#include <math.h>
#include <stdint.h>

// ---------------- problem constants ----------------
#define DD      12288      // C*P*P
#define DHALF   6144
#define KKR     16
#define NPATCH  512        // B * N
#define NTRI    136
#define NPAIR   72         // packed upper-tri pairs
#define GCONST  22583.833392118315f   // d*log(2*pi)
#define DYCNT   86016      // B*C*7*W
#define BCNT    172032

typedef unsigned long long ull;

// ---------------- f32x2 helpers (FFMA2 path, PTX-only) ----------------
__device__ __forceinline__ ull pack2(float lo, float hi) {
    ull r; asm("mov.b64 %0, {%1, %2};" : "=l"(r) : "f"(lo), "f"(hi)); return r;
}
__device__ __forceinline__ void unpack2(ull v, float& lo, float& hi) {
    float a, b;
    asm("mov.b64 {%0, %1}, %2;" : "=f"(a), "=f"(b) : "l"(v));
    lo = a; hi = b;
}
__device__ __forceinline__ void ffma2(ull& d, ull a, ull b) {
    asm("fma.rn.f32x2 %0, %1, %2, %0;" : "+l"(d) : "l"(a), "l"(b));
}
__device__ __forceinline__ ull mul2(ull a, ull b) {
    ull r; asm("mul.rn.f32x2 %0, %1, %2;" : "=l"(r) : "l"(a), "l"(b)); return r;
}
__device__ __forceinline__ ull add2(ull a, ull b) {
    ull r; asm("add.rn.f32x2 %0, %1, %2;" : "=l"(r) : "l"(a), "l"(b)); return r;
}

// ---------------- global scratch (no allocations allowed) ----------------
struct Accums {
    float recon_sum;
    float v2_sum;
    float sig_sum;
    float sigpen_sum;
    float bsum;
    int   sig_min_bits;
};
__device__ Accums g_acc;
// per-patch partials: [0..135]=S upper-tri, [136..151]=u, 152=rDr, 153=logD
__device__ float g_part[NPATCH][160];

__global__ void init_kernel() {
    const int id = blockIdx.x * blockDim.x + threadIdx.x;
    float* gp = &g_part[0][0];
    if (id < NPATCH * 160) gp[id] = 0.f;
    if (id == 0) {
        g_acc.recon_sum = 0.f;
        g_acc.v2_sum = 0.f;
        g_acc.sig_sum = 0.f;
        g_acc.sigpen_sum = 0.f;
        g_acc.bsum = 0.f;
        g_acc.sig_min_bits = 0x7F800000;   // +inf
    }
}

// ---------------- main accumulation kernel ----------------
// 2 blocks per patch (d halves), 128 threads each. Each thread accumulates
// the packed upper-tri Gram of G = diag(1/sqrt(sigma)) V  (72 f32x2 pairs),
// u = G^T (r/sqrt(sigma)) (8 pairs), plus scalars, over its strided d-slice.
__global__ __launch_bounds__(128, 2)
void patch_kernel(const float* __restrict__ x0,
                  const float* __restrict__ mu,
                  const float* __restrict__ sigma,
                  const float* __restrict__ V)
{
    const int p    = blockIdx.x >> 1;
    const int half = blockIdx.x & 1;
    const int b  = p >> 6;
    const int n  = p & 63;
    const int gh = n >> 3;
    const int gwn = n & 7;
    const int t  = threadIdx.x;

    const size_t pbase = (size_t)p * DD;
    const float* __restrict__ mu_p = mu + pbase;
    const float* __restrict__ sg_p = sigma + pbase;
    const float* __restrict__ V_p  = V + pbase * KKR;

    ull Sp[NPAIR];
    ull up[8];
    ull v2p = 0ull;
#pragma unroll
    for (int i = 0; i < NPAIR; i++) Sp[i] = 0ull;
#pragma unroll
    for (int i = 0; i < 8; i++) up[i] = 0ull;
    float rDr = 0.f, logD = 0.f, ssum = 0.f, spen = 0.f;
    float smin = INFINITY;

    const int dend = half * DHALF + DHALF;
    for (int d = half * DHALF + t; d < dend; d += 128) {
        const float sg = sg_p[d];
        const float m  = mu_p[d];
        const int c  = d >> 12;
        const int rm = d & 4095;
        const int py = rm >> 6;
        const int px = rm & 63;
        const float x = x0[((size_t)((b * 3 + c) * 512 + gh * 64 + py)) * 512
                           + (size_t)(gwn * 64 + px)];

        const ulonglong2* __restrict__ vp =
            (const ulonglong2*)(V_p + (size_t)d * 16);
        const ulonglong2 q0 = vp[0], q1 = vp[1], q2 = vp[2], q3 = vp[3];

        const float sw = rsqrtf(sg);
        const float rs = (x - m) * sw;
        rDr  = fmaf(rs, rs, rDr);
        logD += __logf(sg);
        ssum += sg;
        smin  = fminf(smin, sg);
        const float t3 = fmaxf(0.3f - sg, 0.f);
        spen = fmaf(t3, t3, spen);

        const ull sw2 = pack2(sw, sw);
        const ull rs2 = pack2(rs, rs);
        ull Gs[8];
        // v2 accumulates off raw V pairs (consumed once, no staging array)
        ffma2(v2p, q0.x, q0.x); ffma2(v2p, q0.y, q0.y);
        ffma2(v2p, q1.x, q1.x); ffma2(v2p, q1.y, q1.y);
        ffma2(v2p, q2.x, q2.x); ffma2(v2p, q2.y, q2.y);
        ffma2(v2p, q3.x, q3.x); ffma2(v2p, q3.y, q3.y);
        Gs[0] = mul2(q0.x, sw2); Gs[1] = mul2(q0.y, sw2);
        Gs[2] = mul2(q1.x, sw2); Gs[3] = mul2(q1.y, sw2);
        Gs[4] = mul2(q2.x, sw2); Gs[5] = mul2(q2.y, sw2);
        Gs[6] = mul2(q3.x, sw2); Gs[7] = mul2(q3.y, sw2);
#pragma unroll
        for (int i = 0; i < 8; i++) ffma2(up[i], Gs[i], rs2);

        int pidx = 0;
#pragma unroll
        for (int k = 0; k < 16; k++) {
            float glo, ghi;
            unpack2(Gs[k >> 1], glo, ghi);      // CSE'd per pair of k
            const float gk = (k & 1) ? ghi : glo;
            const ull ab = pack2(gk, gk);
#pragma unroll
            for (int mm = (k >> 1); mm < 8; mm++) {
                ffma2(Sp[pidx++], ab, Gs[mm]);   // S[k][2mm..2mm+1]
            }
        }
    }

    // ---- warp butterfly reduction (packed adds) ----
#pragma unroll
    for (int o = 16; o > 0; o >>= 1) {
#pragma unroll
        for (int i = 0; i < NPAIR; i++)
            Sp[i] = add2(Sp[i], __shfl_xor_sync(0xFFFFFFFFu, Sp[i], o));
#pragma unroll
        for (int i = 0; i < 8; i++)
            up[i] = add2(up[i], __shfl_xor_sync(0xFFFFFFFFu, up[i], o));
        v2p = add2(v2p, __shfl_xor_sync(0xFFFFFFFFu, v2p, o));
        rDr  += __shfl_xor_sync(0xFFFFFFFFu, rDr,  o);
        logD += __shfl_xor_sync(0xFFFFFFFFu, logD, o);
        ssum += __shfl_xor_sync(0xFFFFFFFFu, ssum, o);
        spen += __shfl_xor_sync(0xFFFFFFFFu, spen, o);
        smin  = fminf(smin, __shfl_xor_sync(0xFFFFFFFFu, smin, o));
    }

    // ---- cross-warp combine in smem ----
    __shared__ float red[4][168];
    const int warp = t >> 5;
    const int lane = t & 31;
    if (lane == 0) {
        float* r = red[warp];
#pragma unroll
        for (int i = 0; i < NPAIR; i++) unpack2(Sp[i], r[2 * i], r[2 * i + 1]);
#pragma unroll
        for (int i = 0; i < 8; i++)
            unpack2(up[i], r[144 + 2 * i], r[144 + 2 * i + 1]);
        r[160] = rDr;
        r[161] = logD;
        float vlo, vhi; unpack2(v2p, vlo, vhi);
        r[162] = vlo + vhi;
        r[163] = ssum;
        r[164] = spen;
        r[165] = smin;
    }
    __syncthreads();

    if (warp == 0) {
        // sum 4 warps
        for (int slot = lane; slot < 166; slot += 32) {
            float s;
            if (slot == 165) {
                s = fminf(fminf(red[0][slot], red[1][slot]),
                          fminf(red[2][slot], red[3][slot]));
            } else {
                s = red[0][slot] + red[1][slot] + red[2][slot] + red[3][slot];
            }
            red[0][slot] = s;
        }
        __syncwarp();

        // dispatch packed S pairs -> packed upper-tri atomics
        for (int pe = lane; pe < NPAIR; pe += 32) {
            int k = 0, c = 0;
            while (true) {
                const int rowp = 8 - (k >> 1);
                if (c + rowp > pe) break;
                c += rowp; k++;
            }
            const int mm = (k >> 1) + (pe - c);
            const float lo = red[0][2 * pe];
            const float hi = red[0][2 * pe + 1];
            const int j0 = 2 * mm;
            const int base = k * 16 - (k * (k - 1)) / 2 - k;  // tri(k,j)=base+j
            if (j0 >= k) atomicAdd(&g_part[p][base + j0], lo);
            atomicAdd(&g_part[p][base + j0 + 1], hi);
        }
        for (int e = lane; e < 16; e += 32)
            atomicAdd(&g_part[p][136 + e], red[0][144 + e]);
        if (lane == 0) {
            atomicAdd(&g_part[p][152], red[0][160]);
            atomicAdd(&g_part[p][153], red[0][161]);
            atomicAdd(&g_acc.v2_sum,     red[0][162]);
            atomicAdd(&g_acc.sig_sum,    red[0][163]);
            atomicAdd(&g_acc.sigpen_sum, red[0][164]);
            atomicMin(&g_acc.sig_min_bits, __float_as_int(red[0][165]));
        }
    }
}

// ---------------- per-patch solve: warp-parallel 16x16 Cholesky ----------------
// One warp per patch. Lane j (and its mirror j+16) holds row j of M.
__global__ void solve_kernel()
{
    const int gw = (blockIdx.x * blockDim.x + threadIdx.x) >> 5;
    if (gw >= NPATCH) return;
    const int lane = threadIdx.x & 31;
    const int j = lane & 15;               // lanes 16..31 mirror 0..15
    const float* __restrict__ gp = g_part[gw];
    const unsigned F = 0xFFFFFFFFu;

    float M[16];
#pragma unroll
    for (int m = 0; m < 16; m++) {
        const int a  = j < m ? j : m;
        const int bb = j < m ? m : j;
        float val = gp[a * 16 - (a * (a - 1)) / 2 + (bb - a)];
        if (m == j) val += 1.0f + 1e-6f;   // + (1+jitter) I
        M[m] = val;
    }

    float myDiag = 1.f;
#pragma unroll
    for (int i = 0; i < 16; i++) {
        const float dg  = __shfl_sync(F, M[i], i);
        const float Lii = sqrtf(dg);
        float col = M[i] / Lii;            // candidate L[j][i] (j>i)
        if (j == i) { col = Lii; myDiag = Lii; }
        if (j >= i) M[i] = col;            // keep finalized rows intact
#pragma unroll
        for (int m = i + 1; m < 16; m++) {
            const float Lmi = __shfl_sync(F, col, m);
            M[m] -= col * Lmi;             // trailing rank-1 update
        }
    }

    // forward solve L y = u ; quad correction = |y|^2
    float s = gp[136 + j];
    float yv = 0.f;
#pragma unroll
    for (int i = 0; i < 16; i++) {
        const float Lii = __shfl_sync(F, M[i], i);
        const float si  = __shfl_sync(F, s, i);
        const float yi  = si / Lii;
        if (j == i) yv = yi;
        if (j > i)  s -= M[i] * yi;
    }

    float qc = yv * yv;
    float lm = 2.0f * __logf(myDiag);
#pragma unroll
    for (int o = 8; o > 0; o >>= 1) {
        qc += __shfl_xor_sync(F, qc, o);
        lm += __shfl_xor_sync(F, lm, o);
    }
    if (lane == 0) {
        const float nll = 0.5f * (gp[152] - qc + gp[153] + lm + GCONST)
                          / (float)DD;
        atomicAdd(&g_acc.recon_sum, nll);
    }
}

// ---------------- boundary loss on unpatchify(mu) ----------------
__global__ void boundary_kernel(const float* __restrict__ mu)
{
    const int id = blockIdx.x * blockDim.x + threadIdx.x;
    float val = 0.f;
    if (id < BCNT) {
        if (id < DYCNT) {
            int e = id;
            const int x = e & 511; e >>= 9;
            const int i = e % 7;  e /= 7;
            const int c = e % 3;
            const int b = e / 3;
            const int gwx = x >> 6;
            const int px  = x & 63;
            const float top = mu[(size_t)(b * 64 + (i + 1) * 8 + gwx) * DD
                                 + c * 4096 + px];
            const float bot = mu[(size_t)(b * 64 + i * 8 + gwx) * DD
                                 + c * 4096 + 63 * 64 + px];
            const float d2 = top - bot;
            val = d2 * d2;
        } else {
            int e = id - DYCNT;
            const int y = e & 511; e >>= 9;
            const int jx = e % 7;  e /= 7;
            const int c = e % 3;
            const int b = e / 3;
            const int ghy = y >> 6;
            const int py  = y & 63;
            const float right = mu[(size_t)(b * 64 + ghy * 8 + (jx + 1)) * DD
                                   + c * 4096 + py * 64 + 0];
            const float left  = mu[(size_t)(b * 64 + ghy * 8 + jx) * DD
                                   + c * 4096 + py * 64 + 63];
            const float d2 = right - left;
            val = d2 * d2;
        }
    }
#pragma unroll
    for (int o = 16; o > 0; o >>= 1)
        val += __shfl_xor_sync(0xFFFFFFFFu, val, o);
    __shared__ float sh[8];
    const int warp = threadIdx.x >> 5;
    const int lane = threadIdx.x & 31;
    if (lane == 0) sh[warp] = val;
    __syncthreads();
    if (threadIdx.x == 0) {
        float tot = 0.f;
        for (int w2 = 0; w2 < 8; w2++) tot += sh[w2];
        atomicAdd(&g_acc.bsum, tot);
    }
}

__global__ void finalize_kernel(float* __restrict__ out)
{
    if (threadIdx.x != 0 || blockIdx.x != 0) return;
    const float recon    = g_acc.recon_sum / (float)NPATCH;
    const float boundary = g_acc.bsum / (12288.0f * 14.0f);
    const float rank     = g_acc.v2_sum /
                           ((float)NPATCH * (float)DD * (float)KKR);
    const float sigpen   = g_acc.sigpen_sum / ((float)NPATCH * (float)DD);
    const float smean    = g_acc.sig_sum / ((float)NPATCH * (float)DD);
    const float smin     = __int_as_float(g_acc.sig_min_bits);
    const float total    = recon + 0.1f * boundary + 0.01f * rank
                           + 0.05f * sigpen;
    out[0] = total;
    out[1] = recon;
    out[2] = boundary;
    out[3] = rank;
    out[4] = sigpen;
    out[5] = smean;
    out[6] = smin;
}

extern "C" void kernel_launch(void* const* d_in, const int* in_sizes, int n_in,
                              void* d_out, int out_size)
{
    const float* x0    = (const float*)d_in[0];
    const float* mu    = (const float*)d_in[1];
    const float* sigma = (const float*)d_in[2];
    const float* V     = (const float*)d_in[3];
    float* out = (float*)d_out;

    init_kernel<<<(NPATCH * 160 + 255) / 256, 256>>>();
    patch_kernel<<<NPATCH * 2, 128>>>(x0, mu, sigma, V);
    boundary_kernel<<<(BCNT + 255) / 256, 256>>>(mu);
    solve_kernel<<<64, 256>>>();
    finalize_kernel<<<1, 32>>>(out);
}